// round 3
// baseline (speedup 1.0000x reference)
#include <cuda_runtime.h>
#include <math.h>

#define SEQ_N 4096
#define BATCH 4
#define CH    1024
#define HEADS 16
#define HD    64
#define M_TOTAL (BATCH * SEQ_N)      // 16384
#define QKV_COLS (3 * CH)            // 3072

// Scratch (device globals: allocation-free per harness rules)
__device__ float g_qkv[(size_t)M_TOTAL * QKV_COLS];   // 192 MB: [qf | kf*valid | v*valid]
__device__ float g_y[(size_t)M_TOTAL * CH];           // 64 MB
__device__ float g_kv[BATCH * HEADS * HD * HD];       // 1 MB
__device__ float g_z[BATCH * HEADS * HD];

// ---------------------------------------------------------------------------
// GEMM: C[M,N] = A[M,K] @ W[N,K]^T + bias[N], optional qkv epilogue.
// 128x128 tile, BK=16, 256 threads, 8x8 micro-tile per thread.
// mode==1: columns [0,C) -> phi; [C,2C) -> phi*valid; [2C,3C) -> *valid.
// mask is int32 (harness casts bool -> int32), nonzero = PAD.
// ---------------------------------------------------------------------------
__global__ void __launch_bounds__(256) gemm_kernel(
    const float* __restrict__ A, const float* __restrict__ W,
    const float* __restrict__ bias, float* __restrict__ C,
    int M, int N, int K, int mode, const int* __restrict__ mask)
{
    __shared__ float As[16][128];
    __shared__ float Bs[16][128];

    const int tid = threadIdx.x;
    const int tx = tid & 15;        // 0..15 -> col groups of 8
    const int ty = tid >> 4;        // 0..15 -> row groups of 8
    const int m0 = blockIdx.y * 128;
    const int n0 = blockIdx.x * 128;

    const float* Ab = A + (size_t)m0 * K;
    const float* Wb = W + (size_t)n0 * K;

    float acc[8][8];
#pragma unroll
    for (int i = 0; i < 8; i++)
#pragma unroll
        for (int j = 0; j < 8; j++) acc[i][j] = 0.f;

    for (int k0 = 0; k0 < K; k0 += 16) {
#pragma unroll
        for (int r = 0; r < 2; r++) {
            int f = tid + r * 256;           // 512 float4 per tile
            int row = f >> 2;                // 0..127
            int kq = (f & 3) << 2;           // 0,4,8,12
            float4 av = *(const float4*)(Ab + (size_t)row * K + k0 + kq);
            As[kq + 0][row] = av.x; As[kq + 1][row] = av.y;
            As[kq + 2][row] = av.z; As[kq + 3][row] = av.w;
            float4 bv = *(const float4*)(Wb + (size_t)row * K + k0 + kq);
            Bs[kq + 0][row] = bv.x; Bs[kq + 1][row] = bv.y;
            Bs[kq + 2][row] = bv.z; Bs[kq + 3][row] = bv.w;
        }
        __syncthreads();

#pragma unroll
        for (int kk = 0; kk < 16; kk++) {
            float a[8], b[8];
            *(float4*)&a[0] = *(const float4*)&As[kk][ty * 8];
            *(float4*)&a[4] = *(const float4*)&As[kk][ty * 8 + 4];
            *(float4*)&b[0] = *(const float4*)&Bs[kk][tx * 8];
            *(float4*)&b[4] = *(const float4*)&Bs[kk][tx * 8 + 4];
#pragma unroll
            for (int i = 0; i < 8; i++)
#pragma unroll
                for (int j = 0; j < 8; j++)
                    acc[i][j] = fmaf(a[i], b[j], acc[i][j]);
        }
        __syncthreads();
    }

    // Epilogue
#pragma unroll
    for (int i = 0; i < 8; i++) {
        const int m = m0 + ty * 8 + i;
        float valid = 1.0f;
        if (mode == 1) valid = (mask[m] != 0) ? 0.0f : 1.0f;
#pragma unroll
        for (int j = 0; j < 8; j += 4) {
            float4 o;
            float* op = &o.x;
#pragma unroll
            for (int q = 0; q < 4; q++) {
                const int n = n0 + tx * 8 + j + q;
                float v = acc[i][j + q] + bias[n];
                if (mode == 1) {
                    if (n < 2 * CH) {                 // q or k -> phi = elu+1
                        v = (v > 0.f) ? (v + 1.0f) : __expf(v);
                        if (n >= CH) v *= valid;      // kf masked
                    } else {
                        v *= valid;                   // v masked
                    }
                }
                op[q] = v;
            }
            *(float4*)(C + (size_t)m * N + n0 + tx * 8 + j) = o;
        }
    }
}

// ---------------------------------------------------------------------------
// Zero kv/z scratch
// ---------------------------------------------------------------------------
__global__ void zero_kernel() {
    int i = blockIdx.x * 256 + threadIdx.x;
    if (i < BATCH * HEADS * HD * HD) g_kv[i] = 0.f;
    if (i < BATCH * HEADS * HD) g_z[i] = 0.f;
}

// ---------------------------------------------------------------------------
// kv[b,h,d,e] = sum_n kf[b,h,n,d] * v[b,h,n,e];  z[b,h,d] = sum_n kf.
// grid (B*H, 8 n-splits), 256 threads, 4x4 micro-tile, atomic reduce.
// ---------------------------------------------------------------------------
__global__ void __launch_bounds__(256) kv_kernel() {
    const int bh = blockIdx.x;
    const int b = bh >> 4, h = bh & 15;
    const int n0 = blockIdx.y * 512;
    const int tid = threadIdx.x;
    const int tx = tid & 15, ty = tid >> 4;

    __shared__ float kf_s[32][64];
    __shared__ float v_s[32][64];

    float acc[4][4];
    float zacc[4];
#pragma unroll
    for (int i = 0; i < 4; i++) {
        zacc[i] = 0.f;
#pragma unroll
        for (int j = 0; j < 4; j++) acc[i][j] = 0.f;
    }

    const float* base = g_qkv + (size_t)(b * SEQ_N + n0) * QKV_COLS + h * HD;

    for (int nt = 0; nt < 512; nt += 32) {
#pragma unroll
        for (int r = 0; r < 8; r++) {
            int e = tid + r * 256;
            int row = e >> 6, col = e & 63;
            size_t g = (size_t)(nt + row) * QKV_COLS + col;
            kf_s[row][col] = base[g + CH];       // kf (masked)
            v_s[row][col]  = base[g + 2 * CH];   // v  (masked)
        }
        __syncthreads();

#pragma unroll 8
        for (int kk = 0; kk < 32; kk++) {
            float a[4], bb[4];
            *(float4*)a  = *(const float4*)&kf_s[kk][ty * 4];
            *(float4*)bb = *(const float4*)&v_s[kk][tx * 4];
#pragma unroll
            for (int i = 0; i < 4; i++) {
                zacc[i] += a[i];
#pragma unroll
                for (int j = 0; j < 4; j++)
                    acc[i][j] = fmaf(a[i], bb[j], acc[i][j]);
            }
        }
        __syncthreads();
    }

    float* kvb = g_kv + (size_t)bh * (HD * HD);
#pragma unroll
    for (int i = 0; i < 4; i++)
#pragma unroll
        for (int j = 0; j < 4; j++)
            atomicAdd(&kvb[(ty * 4 + i) * HD + tx * 4 + j], acc[i][j]);
    if (tx == 0) {
#pragma unroll
        for (int i = 0; i < 4; i++)
            atomicAdd(&g_z[bh * HD + ty * 4 + i], zacc[i]);
    }
}

// ---------------------------------------------------------------------------
// y[b,n,h*64+e] = (qf[b,h,n,:] @ kv[b,h,:,e]) / max(qf[b,h,n,:]·z[b,h,:], EPS)
// grid (B*H, N/32), 256 threads: thread = (n_local=tid/8, e_group=(tid&7)*8)
// ---------------------------------------------------------------------------
__global__ void __launch_bounds__(256) y_kernel() {
    const int bh = blockIdx.x;
    const int b = bh >> 4, h = bh & 15;
    const int n0 = blockIdx.y * 32;
    const int tid = threadIdx.x;

    __shared__ float kvs[64][64];
    __shared__ float zs[64];
    __shared__ float qs[32][68];   // padded to avoid bank conflicts on row reads

    const float* kvb = g_kv + (size_t)bh * (HD * HD);
#pragma unroll
    for (int r = 0; r < 16; r++) {
        int e = tid + r * 256;
        kvs[e >> 6][e & 63] = kvb[e];
    }
    if (tid < 64) zs[tid] = g_z[bh * HD + tid];

    const float* qbase = g_qkv + (size_t)(b * SEQ_N + n0) * QKV_COLS + h * HD;
#pragma unroll
    for (int r = 0; r < 8; r++) {
        int e = tid + r * 256;
        int row = e >> 6, col = e & 63;
        qs[row][col] = qbase[(size_t)row * QKV_COLS + col];
    }
    __syncthreads();

    const int nl = tid >> 3;             // 0..31
    const int eg = (tid & 7) * 8;        // 0..56

    float acc[8];
#pragma unroll
    for (int j = 0; j < 8; j++) acc[j] = 0.f;
    float den = 0.f;

#pragma unroll 8
    for (int d = 0; d < 64; d++) {
        float q = qs[nl][d];
        den = fmaf(q, zs[d], den);
        float bb[8];
        *(float4*)&bb[0] = *(const float4*)&kvs[d][eg];
        *(float4*)&bb[4] = *(const float4*)&kvs[d][eg + 4];
#pragma unroll
        for (int j = 0; j < 8; j++)
            acc[j] = fmaf(q, bb[j], acc[j]);
    }

    const float inv = 1.0f / fmaxf(den, 1e-6f);
    float* yp = g_y + (size_t)(b * SEQ_N + n0 + nl) * CH + h * HD + eg;
    float4 o0 = make_float4(acc[0] * inv, acc[1] * inv, acc[2] * inv, acc[3] * inv);
    float4 o1 = make_float4(acc[4] * inv, acc[5] * inv, acc[6] * inv, acc[7] * inv);
    *(float4*)yp = o0;
    *(float4*)(yp + 4) = o1;
}

// ---------------------------------------------------------------------------
extern "C" void kernel_launch(void* const* d_in, const int* in_sizes, int n_in,
                              void* d_out, int out_size)
{
    const float* x     = (const float*)d_in[0];   // [B,N,C]
    const float* W_qkv = (const float*)d_in[1];   // [3C,C]
    const float* b_qkv = (const float*)d_in[2];   // [3C]
    const float* W_out = (const float*)d_in[3];   // [C,C]
    const float* b_out = (const float*)d_in[4];   // [C]
    const int*   mask  = (const int*)d_in[5];     // [B,N] bool->int32, nonzero=PAD

    float* qkv_p; float* y_p;
    cudaGetSymbolAddress((void**)&qkv_p, g_qkv);
    cudaGetSymbolAddress((void**)&y_p, g_y);

    // 1) QKV projection + bias + phi + mask epilogue
    {
        dim3 grid(QKV_COLS / 128, M_TOTAL / 128);
        gemm_kernel<<<grid, 256>>>(x, W_qkv, b_qkv, qkv_p,
                                   M_TOTAL, QKV_COLS, CH, 1, mask);
    }

    // 2) zero kv/z scratch
    zero_kernel<<<(BATCH * HEADS * HD * HD + 255) / 256, 256>>>();

    // 3) kv state + z
    {
        dim3 grid(BATCH * HEADS, SEQ_N / 512);
        kv_kernel<<<grid, 256>>>();
    }

    // 4) y = (qf @ kv) / den, re-layout to [B,N,C]
    {
        dim3 grid(BATCH * HEADS, SEQ_N / 32);
        y_kernel<<<grid, 256>>>();
    }

    // 5) output projection
    {
        dim3 grid(CH / 128, M_TOTAL / 128);
        gemm_kernel<<<grid, 256>>>(y_p, W_out, b_out, (float*)d_out,
                                   M_TOTAL, CH, CH, 0, nullptr);
    }
}

// round 4
// speedup vs baseline: 1.0003x; 1.0003x over previous
#include <cuda_runtime.h>
#include <math.h>

#define SEQ_N 4096
#define BATCH 4
#define CH    1024
#define HEADS 16
#define HD    64
#define M_TOTAL (BATCH * SEQ_N)      // 16384
#define QKV_COLS (3 * CH)            // 3072

// Scratch (device globals: allocation-free per harness rules)
__device__ float g_qkv[(size_t)M_TOTAL * QKV_COLS];   // 192 MB: [qf | kf*valid | v*valid]
__device__ float g_y[(size_t)M_TOTAL * CH];           // 64 MB
__device__ float g_kv[BATCH * HEADS * HD * HD];       // 1 MB
__device__ float g_z[BATCH * HEADS * HD];

// ---------------------------------------------------------------------------
// GEMM: C[M,N] = A[M,K] @ W[N,K]^T + bias[N], optional qkv epilogue.
// 128x128 tile, BK=16, 256 threads, 8x8 micro-tile per thread.
// mode==1: columns [0,C) -> phi; [C,2C) -> phi*valid; [2C,3C) -> *valid.
// mask is int32 (harness casts bool -> int32), nonzero = PAD.
// ---------------------------------------------------------------------------
__global__ void __launch_bounds__(256) gemm_kernel(
    const float* __restrict__ A, const float* __restrict__ W,
    const float* __restrict__ bias, float* __restrict__ C,
    int M, int N, int K, int mode, const int* __restrict__ mask)
{
    __shared__ float As[16][128];
    __shared__ float Bs[16][128];

    const int tid = threadIdx.x;
    const int tx = tid & 15;        // 0..15 -> col groups of 8
    const int ty = tid >> 4;        // 0..15 -> row groups of 8
    const int m0 = blockIdx.y * 128;
    const int n0 = blockIdx.x * 128;

    const float* Ab = A + (size_t)m0 * K;
    const float* Wb = W + (size_t)n0 * K;

    float acc[8][8];
#pragma unroll
    for (int i = 0; i < 8; i++)
#pragma unroll
        for (int j = 0; j < 8; j++) acc[i][j] = 0.f;

    for (int k0 = 0; k0 < K; k0 += 16) {
#pragma unroll
        for (int r = 0; r < 2; r++) {
            int f = tid + r * 256;           // 512 float4 per tile
            int row = f >> 2;                // 0..127
            int kq = (f & 3) << 2;           // 0,4,8,12
            float4 av = *(const float4*)(Ab + (size_t)row * K + k0 + kq);
            As[kq + 0][row] = av.x; As[kq + 1][row] = av.y;
            As[kq + 2][row] = av.z; As[kq + 3][row] = av.w;
            float4 bv = *(const float4*)(Wb + (size_t)row * K + k0 + kq);
            Bs[kq + 0][row] = bv.x; Bs[kq + 1][row] = bv.y;
            Bs[kq + 2][row] = bv.z; Bs[kq + 3][row] = bv.w;
        }
        __syncthreads();

#pragma unroll
        for (int kk = 0; kk < 16; kk++) {
            float a[8], b[8];
            *(float4*)&a[0] = *(const float4*)&As[kk][ty * 8];
            *(float4*)&a[4] = *(const float4*)&As[kk][ty * 8 + 4];
            *(float4*)&b[0] = *(const float4*)&Bs[kk][tx * 8];
            *(float4*)&b[4] = *(const float4*)&Bs[kk][tx * 8 + 4];
#pragma unroll
            for (int i = 0; i < 8; i++)
#pragma unroll
                for (int j = 0; j < 8; j++)
                    acc[i][j] = fmaf(a[i], b[j], acc[i][j]);
        }
        __syncthreads();
    }

    // Epilogue
#pragma unroll
    for (int i = 0; i < 8; i++) {
        const int m = m0 + ty * 8 + i;
        float valid = 1.0f;
        if (mode == 1) valid = (mask[m] != 0) ? 0.0f : 1.0f;
#pragma unroll
        for (int j = 0; j < 8; j += 4) {
            float4 o;
            float* op = &o.x;
#pragma unroll
            for (int q = 0; q < 4; q++) {
                const int n = n0 + tx * 8 + j + q;
                float v = acc[i][j + q] + bias[n];
                if (mode == 1) {
                    if (n < 2 * CH) {                 // q or k -> phi = elu+1
                        v = (v > 0.f) ? (v + 1.0f) : __expf(v);
                        if (n >= CH) v *= valid;      // kf masked
                    } else {
                        v *= valid;                   // v masked
                    }
                }
                op[q] = v;
            }
            *(float4*)(C + (size_t)m * N + n0 + tx * 8 + j) = o;
        }
    }
}

// ---------------------------------------------------------------------------
// Zero kv/z scratch
// ---------------------------------------------------------------------------
__global__ void zero_kernel() {
    int i = blockIdx.x * 256 + threadIdx.x;
    if (i < BATCH * HEADS * HD * HD) g_kv[i] = 0.f;
    if (i < BATCH * HEADS * HD) g_z[i] = 0.f;
}

// ---------------------------------------------------------------------------
// kv[b,h,d,e] = sum_n kf[b,h,n,d] * v[b,h,n,e];  z[b,h,d] = sum_n kf.
// grid (B*H, 8 n-splits), 256 threads, 4x4 micro-tile, atomic reduce.
// ---------------------------------------------------------------------------
__global__ void __launch_bounds__(256) kv_kernel() {
    const int bh = blockIdx.x;
    const int b = bh >> 4, h = bh & 15;
    const int n0 = blockIdx.y * 512;
    const int tid = threadIdx.x;
    const int tx = tid & 15, ty = tid >> 4;

    __shared__ float kf_s[32][64];
    __shared__ float v_s[32][64];

    float acc[4][4];
    float zacc[4];
#pragma unroll
    for (int i = 0; i < 4; i++) {
        zacc[i] = 0.f;
#pragma unroll
        for (int j = 0; j < 4; j++) acc[i][j] = 0.f;
    }

    const float* base = g_qkv + (size_t)(b * SEQ_N + n0) * QKV_COLS + h * HD;

    for (int nt = 0; nt < 512; nt += 32) {
#pragma unroll
        for (int r = 0; r < 8; r++) {
            int e = tid + r * 256;
            int row = e >> 6, col = e & 63;
            size_t g = (size_t)(nt + row) * QKV_COLS + col;
            kf_s[row][col] = base[g + CH];       // kf (masked)
            v_s[row][col]  = base[g + 2 * CH];   // v  (masked)
        }
        __syncthreads();

#pragma unroll 8
        for (int kk = 0; kk < 32; kk++) {
            float a[4], bb[4];
            *(float4*)a  = *(const float4*)&kf_s[kk][ty * 4];
            *(float4*)bb = *(const float4*)&v_s[kk][tx * 4];
#pragma unroll
            for (int i = 0; i < 4; i++) {
                zacc[i] += a[i];
#pragma unroll
                for (int j = 0; j < 4; j++)
                    acc[i][j] = fmaf(a[i], bb[j], acc[i][j]);
            }
        }
        __syncthreads();
    }

    float* kvb = g_kv + (size_t)bh * (HD * HD);
#pragma unroll
    for (int i = 0; i < 4; i++)
#pragma unroll
        for (int j = 0; j < 4; j++)
            atomicAdd(&kvb[(ty * 4 + i) * HD + tx * 4 + j], acc[i][j]);
    if (tx == 0) {
#pragma unroll
        for (int i = 0; i < 4; i++)
            atomicAdd(&g_z[bh * HD + ty * 4 + i], zacc[i]);
    }
}

// ---------------------------------------------------------------------------
// y[b,n,h*64+e] = (qf[b,h,n,:] @ kv[b,h,:,e]) / max(qf[b,h,n,:]·z[b,h,:], EPS)
// grid (B*H, N/32), 256 threads: thread = (n_local=tid/8, e_group=(tid&7)*8)
// ---------------------------------------------------------------------------
__global__ void __launch_bounds__(256) y_kernel() {
    const int bh = blockIdx.x;
    const int b = bh >> 4, h = bh & 15;
    const int n0 = blockIdx.y * 32;
    const int tid = threadIdx.x;

    __shared__ float kvs[64][64];
    __shared__ float zs[64];
    __shared__ float qs[32][68];   // padded to avoid bank conflicts on row reads

    const float* kvb = g_kv + (size_t)bh * (HD * HD);
#pragma unroll
    for (int r = 0; r < 16; r++) {
        int e = tid + r * 256;
        kvs[e >> 6][e & 63] = kvb[e];
    }
    if (tid < 64) zs[tid] = g_z[bh * HD + tid];

    const float* qbase = g_qkv + (size_t)(b * SEQ_N + n0) * QKV_COLS + h * HD;
#pragma unroll
    for (int r = 0; r < 8; r++) {
        int e = tid + r * 256;
        int row = e >> 6, col = e & 63;
        qs[row][col] = qbase[(size_t)row * QKV_COLS + col];
    }
    __syncthreads();

    const int nl = tid >> 3;             // 0..31
    const int eg = (tid & 7) * 8;        // 0..56

    float acc[8];
#pragma unroll
    for (int j = 0; j < 8; j++) acc[j] = 0.f;
    float den = 0.f;

#pragma unroll 8
    for (int d = 0; d < 64; d++) {
        float q = qs[nl][d];
        den = fmaf(q, zs[d], den);
        float bb[8];
        *(float4*)&bb[0] = *(const float4*)&kvs[d][eg];
        *(float4*)&bb[4] = *(const float4*)&kvs[d][eg + 4];
#pragma unroll
        for (int j = 0; j < 8; j++)
            acc[j] = fmaf(q, bb[j], acc[j]);
    }

    const float inv = 1.0f / fmaxf(den, 1e-6f);
    float* yp = g_y + (size_t)(b * SEQ_N + n0 + nl) * CH + h * HD + eg;
    float4 o0 = make_float4(acc[0] * inv, acc[1] * inv, acc[2] * inv, acc[3] * inv);
    float4 o1 = make_float4(acc[4] * inv, acc[5] * inv, acc[6] * inv, acc[7] * inv);
    *(float4*)yp = o0;
    *(float4*)(yp + 4) = o1;
}

// ---------------------------------------------------------------------------
extern "C" void kernel_launch(void* const* d_in, const int* in_sizes, int n_in,
                              void* d_out, int out_size)
{
    const float* x     = (const float*)d_in[0];   // [B,N,C]
    const float* W_qkv = (const float*)d_in[1];   // [3C,C]
    const float* b_qkv = (const float*)d_in[2];   // [3C]
    const float* W_out = (const float*)d_in[3];   // [C,C]
    const float* b_out = (const float*)d_in[4];   // [C]
    const int*   mask  = (const int*)d_in[5];     // [B,N] bool->int32, nonzero=PAD

    float* qkv_p; float* y_p;
    cudaGetSymbolAddress((void**)&qkv_p, g_qkv);
    cudaGetSymbolAddress((void**)&y_p, g_y);

    // 1) QKV projection + bias + phi + mask epilogue
    {
        dim3 grid(QKV_COLS / 128, M_TOTAL / 128);
        gemm_kernel<<<grid, 256>>>(x, W_qkv, b_qkv, qkv_p,
                                   M_TOTAL, QKV_COLS, CH, 1, mask);
    }

    // 2) zero kv/z scratch
    zero_kernel<<<(BATCH * HEADS * HD * HD + 255) / 256, 256>>>();

    // 3) kv state + z
    {
        dim3 grid(BATCH * HEADS, SEQ_N / 512);
        kv_kernel<<<grid, 256>>>();
    }

    // 4) y = (qf @ kv) / den, re-layout to [B,N,C]
    {
        dim3 grid(BATCH * HEADS, SEQ_N / 32);
        y_kernel<<<grid, 256>>>();
    }

    // 5) output projection
    {
        dim3 grid(CH / 128, M_TOTAL / 128);
        gemm_kernel<<<grid, 256>>>(y_p, W_out, b_out, (float*)d_out,
                                   M_TOTAL, CH, CH, 0, nullptr);
    }
}

// round 5
// speedup vs baseline: 2.2058x; 2.2050x over previous
#include <cuda_runtime.h>
#include <math.h>

#define SEQ_N 4096
#define BATCH 4
#define CH    1024
#define HEADS 16
#define HD    64
#define M_TOTAL (BATCH * SEQ_N)      // 16384
#define QKV_COLS (3 * CH)            // 3072

// Scratch (device globals: allocation-free per harness rules)
__device__ float g_qkv[(size_t)M_TOTAL * QKV_COLS];   // 192 MB: [qf | kf*valid | v*valid]
__device__ float g_y[(size_t)M_TOTAL * CH];           // 64 MB
__device__ float g_kv[BATCH * HEADS * HD * HD];       // 1 MB
__device__ float g_z[BATCH * HEADS * HD];

// ---------------------------------------------------------------------------
// tf32 tensor-core GEMM: C[M,N] = A[M,K] @ W[N,K]^T + bias[N] (+ qkv epilogue)
// 128x128x32 CTA tile, 256 threads, warp grid 2(M)x4(N), warp tile 64x32.
// mma.sync.aligned.m16n8k8.row.col.f32.tf32.tf32.f32.
// Smem k-pair permutation: within each k8 group, pos = (k&3)*2 + ((k>>2)&1),
// so fragment pairs (k=t, k=t+4) sit adjacent -> one LDS.64 per fragment pair.
// mode==1: columns [0,C) -> phi; [C,2C) -> phi*valid; [2C,3C) -> *valid.
// mask is int32 (bool cast), nonzero = PAD.
// ---------------------------------------------------------------------------
#define ASTRIDE 40   // 32 used + 8 pad words: conflict-free LDS.64 phases

__device__ __forceinline__ unsigned f2tf32(float f) {
    unsigned r;
    asm("cvt.rna.tf32.f32 %0, %1;" : "=r"(r) : "f"(f));
    return r;
}

__global__ void __launch_bounds__(256) gemm_tf32_kernel(
    const float* __restrict__ A, const float* __restrict__ W,
    const float* __restrict__ bias, float* __restrict__ C,
    int M, int N, int K, int mode, const int* __restrict__ mask)
{
    __shared__ __align__(16) unsigned As[128 * ASTRIDE];
    __shared__ __align__(16) unsigned Bs[128 * ASTRIDE];

    const int tid  = threadIdx.x;
    const int lane = tid & 31;
    const int wid  = tid >> 5;
    const int warp_m = wid & 1;     // 0..1  -> 64-row slice
    const int warp_n = wid >> 1;    // 0..3  -> 32-col slice
    const int g = lane >> 2;        // 0..7
    const int t = lane & 3;         // 0..3

    const int m0 = blockIdx.y * 128;
    const int n0 = blockIdx.x * 128;

    const float* Ab = A + (size_t)m0 * K;
    const float* Wb = W + (size_t)n0 * K;

    float acc[4][4][4];             // [mt][nt][c0..c3]
#pragma unroll
    for (int mt = 0; mt < 4; mt++)
#pragma unroll
        for (int nt = 0; nt < 4; nt++)
#pragma unroll
            for (int c = 0; c < 4; c++) acc[mt][nt][c] = 0.f;

    for (int k0 = 0; k0 < K; k0 += 32) {
        // ---- gmem -> smem (tf32-converted, k-pair permuted) ----
#pragma unroll
        for (int r = 0; r < 4; r++) {
            int f = tid + r * 256;          // 0..1023
            int row = f >> 3;               // 0..127
            int kb = (f & 7) << 2;          // 0,4,...,28
            int grp = (kb >> 3) * 8;        // k8 group base
            int hi = (kb >> 2) & 1;         // which half of the group
            {
                float4 v = *(const float4*)(Ab + (size_t)row * K + k0 + kb);
                unsigned* p = &As[row * ASTRIDE + grp + hi];
                p[0] = f2tf32(v.x); p[2] = f2tf32(v.y);
                p[4] = f2tf32(v.z); p[6] = f2tf32(v.w);
            }
            {
                float4 v = *(const float4*)(Wb + (size_t)row * K + k0 + kb);
                unsigned* p = &Bs[row * ASTRIDE + grp + hi];
                p[0] = f2tf32(v.x); p[2] = f2tf32(v.y);
                p[4] = f2tf32(v.z); p[6] = f2tf32(v.w);
            }
        }
        __syncthreads();

        // ---- 4 k8 steps of mma ----
#pragma unroll
        for (int kt = 0; kt < 4; kt++) {
            unsigned a[4][4], b[4][2];
#pragma unroll
            for (int mt = 0; mt < 4; mt++) {
                int row = warp_m * 64 + mt * 16 + g;
                uint2 lo = *(const uint2*)&As[row * ASTRIDE + kt * 8 + 2 * t];
                uint2 hi = *(const uint2*)&As[(row + 8) * ASTRIDE + kt * 8 + 2 * t];
                a[mt][0] = lo.x; a[mt][1] = hi.x; a[mt][2] = lo.y; a[mt][3] = hi.y;
            }
#pragma unroll
            for (int nt = 0; nt < 4; nt++) {
                int rn = warp_n * 32 + nt * 8 + g;
                uint2 bb = *(const uint2*)&Bs[rn * ASTRIDE + kt * 8 + 2 * t];
                b[nt][0] = bb.x; b[nt][1] = bb.y;
            }
#pragma unroll
            for (int mt = 0; mt < 4; mt++)
#pragma unroll
                for (int nt = 0; nt < 4; nt++) {
                    asm volatile(
                        "mma.sync.aligned.m16n8k8.row.col.f32.tf32.tf32.f32 "
                        "{%0,%1,%2,%3}, {%4,%5,%6,%7}, {%8,%9}, {%0,%1,%2,%3};"
                        : "+f"(acc[mt][nt][0]), "+f"(acc[mt][nt][1]),
                          "+f"(acc[mt][nt][2]), "+f"(acc[mt][nt][3])
                        : "r"(a[mt][0]), "r"(a[mt][1]), "r"(a[mt][2]), "r"(a[mt][3]),
                          "r"(b[nt][0]), "r"(b[nt][1]));
                }
        }
        __syncthreads();
    }

    // ---- epilogue: bias + (phi / mask) + store ----
#pragma unroll
    for (int mt = 0; mt < 4; mt++) {
        const int mr0 = m0 + warp_m * 64 + mt * 16 + g;   // rows mr0, mr0+8
        float valid0 = 1.0f, valid1 = 1.0f;
        if (mode == 1) {
            valid0 = (mask[mr0] != 0) ? 0.0f : 1.0f;
            valid1 = (mask[mr0 + 8] != 0) ? 0.0f : 1.0f;
        }
#pragma unroll
        for (int nt = 0; nt < 4; nt++) {
            const int nc = n0 + warp_n * 32 + nt * 8 + 2 * t;
            float bx = bias[nc], by = bias[nc + 1];
            float v0 = acc[mt][nt][0] + bx;   // (mr0,   nc)
            float v1 = acc[mt][nt][1] + by;   // (mr0,   nc+1)
            float v2 = acc[mt][nt][2] + bx;   // (mr0+8, nc)
            float v3 = acc[mt][nt][3] + by;   // (mr0+8, nc+1)
            if (mode == 1) {
                // nc is even; nc and nc+1 are always in the same 1024-column
                // region (q / k / v), so one region test covers both.
                if (nc < 2 * CH) {            // q or k -> phi = elu+1
                    v0 = (v0 > 0.f) ? (v0 + 1.0f) : __expf(v0);
                    v1 = (v1 > 0.f) ? (v1 + 1.0f) : __expf(v1);
                    v2 = (v2 > 0.f) ? (v2 + 1.0f) : __expf(v2);
                    v3 = (v3 > 0.f) ? (v3 + 1.0f) : __expf(v3);
                    if (nc >= CH) {           // kf masked
                        v0 *= valid0; v1 *= valid0;
                        v2 *= valid1; v3 *= valid1;
                    }
                } else {                      // v masked
                    v0 *= valid0; v1 *= valid0;
                    v2 *= valid1; v3 *= valid1;
                }
            }
            *(float2*)(C + (size_t)mr0 * N + nc)       = make_float2(v0, v1);
            *(float2*)(C + (size_t)(mr0 + 8) * N + nc) = make_float2(v2, v3);
        }
    }
}

// ---------------------------------------------------------------------------
// Zero kv/z scratch
// ---------------------------------------------------------------------------
__global__ void zero_kernel() {
    int i = blockIdx.x * 256 + threadIdx.x;
    if (i < BATCH * HEADS * HD * HD) g_kv[i] = 0.f;
    if (i < BATCH * HEADS * HD) g_z[i] = 0.f;
}

// ---------------------------------------------------------------------------
// kv[b,h,d,e] = sum_n kf[b,h,n,d] * v[b,h,n,e];  z[b,h,d] = sum_n kf.
// grid (B*H, 8 n-splits), 256 threads, 4x4 micro-tile, atomic reduce. (fp32)
// ---------------------------------------------------------------------------
__global__ void __launch_bounds__(256) kv_kernel() {
    const int bh = blockIdx.x;
    const int b = bh >> 4, h = bh & 15;
    const int n0 = blockIdx.y * 512;
    const int tid = threadIdx.x;
    const int tx = tid & 15, ty = tid >> 4;

    __shared__ float kf_s[32][64];
    __shared__ float v_s[32][64];

    float acc[4][4];
    float zacc[4];
#pragma unroll
    for (int i = 0; i < 4; i++) {
        zacc[i] = 0.f;
#pragma unroll
        for (int j = 0; j < 4; j++) acc[i][j] = 0.f;
    }

    const float* base = g_qkv + (size_t)(b * SEQ_N + n0) * QKV_COLS + h * HD;

    for (int nt = 0; nt < 512; nt += 32) {
#pragma unroll
        for (int r = 0; r < 8; r++) {
            int e = tid + r * 256;
            int row = e >> 6, col = e & 63;
            size_t gidx = (size_t)(nt + row) * QKV_COLS + col;
            kf_s[row][col] = base[gidx + CH];       // kf (masked)
            v_s[row][col]  = base[gidx + 2 * CH];   // v  (masked)
        }
        __syncthreads();

#pragma unroll 8
        for (int kk = 0; kk < 32; kk++) {
            float a[4], bb[4];
            *(float4*)a  = *(const float4*)&kf_s[kk][ty * 4];
            *(float4*)bb = *(const float4*)&v_s[kk][tx * 4];
#pragma unroll
            for (int i = 0; i < 4; i++) {
                zacc[i] += a[i];
#pragma unroll
                for (int j = 0; j < 4; j++)
                    acc[i][j] = fmaf(a[i], bb[j], acc[i][j]);
            }
        }
        __syncthreads();
    }

    float* kvb = g_kv + (size_t)bh * (HD * HD);
#pragma unroll
    for (int i = 0; i < 4; i++)
#pragma unroll
        for (int j = 0; j < 4; j++)
            atomicAdd(&kvb[(ty * 4 + i) * HD + tx * 4 + j], acc[i][j]);
    if (tx == 0) {
#pragma unroll
        for (int i = 0; i < 4; i++)
            atomicAdd(&g_z[bh * HD + ty * 4 + i], zacc[i]);
    }
}

// ---------------------------------------------------------------------------
// y[b,n,h*64+e] = (qf[b,h,n,:] @ kv[b,h,:,e]) / max(qf[b,h,n,:]·z[b,h,:], EPS)
// grid (B*H, N/32), 256 threads. (fp32)
// ---------------------------------------------------------------------------
__global__ void __launch_bounds__(256) y_kernel() {
    const int bh = blockIdx.x;
    const int b = bh >> 4, h = bh & 15;
    const int n0 = blockIdx.y * 32;
    const int tid = threadIdx.x;

    __shared__ float kvs[64][64];
    __shared__ float zs[64];
    __shared__ float qs[32][68];

    const float* kvb = g_kv + (size_t)bh * (HD * HD);
#pragma unroll
    for (int r = 0; r < 16; r++) {
        int e = tid + r * 256;
        kvs[e >> 6][e & 63] = kvb[e];
    }
    if (tid < 64) zs[tid] = g_z[bh * HD + tid];

    const float* qbase = g_qkv + (size_t)(b * SEQ_N + n0) * QKV_COLS + h * HD;
#pragma unroll
    for (int r = 0; r < 8; r++) {
        int e = tid + r * 256;
        int row = e >> 6, col = e & 63;
        qs[row][col] = qbase[(size_t)row * QKV_COLS + col];
    }
    __syncthreads();

    const int nl = tid >> 3;
    const int eg = (tid & 7) * 8;

    float acc[8];
#pragma unroll
    for (int j = 0; j < 8; j++) acc[j] = 0.f;
    float den = 0.f;

#pragma unroll 8
    for (int d = 0; d < 64; d++) {
        float q = qs[nl][d];
        den = fmaf(q, zs[d], den);
        float bb[8];
        *(float4*)&bb[0] = *(const float4*)&kvs[d][eg];
        *(float4*)&bb[4] = *(const float4*)&kvs[d][eg + 4];
#pragma unroll
        for (int j = 0; j < 8; j++)
            acc[j] = fmaf(q, bb[j], acc[j]);
    }

    const float inv = 1.0f / fmaxf(den, 1e-6f);
    float* yp = g_y + (size_t)(b * SEQ_N + n0 + nl) * CH + h * HD + eg;
    float4 o0 = make_float4(acc[0] * inv, acc[1] * inv, acc[2] * inv, acc[3] * inv);
    float4 o1 = make_float4(acc[4] * inv, acc[5] * inv, acc[6] * inv, acc[7] * inv);
    *(float4*)yp = o0;
    *(float4*)(yp + 4) = o1;
}

// ---------------------------------------------------------------------------
extern "C" void kernel_launch(void* const* d_in, const int* in_sizes, int n_in,
                              void* d_out, int out_size)
{
    const float* x     = (const float*)d_in[0];   // [B,N,C]
    const float* W_qkv = (const float*)d_in[1];   // [3C,C]
    const float* b_qkv = (const float*)d_in[2];   // [3C]
    const float* W_out = (const float*)d_in[3];   // [C,C]
    const float* b_out = (const float*)d_in[4];   // [C]
    const int*   mask  = (const int*)d_in[5];     // [B,N] bool->int32, nonzero=PAD

    float* qkv_p; float* y_p;
    cudaGetSymbolAddress((void**)&qkv_p, g_qkv);
    cudaGetSymbolAddress((void**)&y_p, g_y);

    // 1) QKV projection + bias + phi + mask epilogue (tf32 tensor cores)
    {
        dim3 grid(QKV_COLS / 128, M_TOTAL / 128);
        gemm_tf32_kernel<<<grid, 256>>>(x, W_qkv, b_qkv, qkv_p,
                                        M_TOTAL, QKV_COLS, CH, 1, mask);
    }

    // 2) zero kv/z scratch
    zero_kernel<<<(BATCH * HEADS * HD * HD + 255) / 256, 256>>>();

    // 3) kv state + z (fp32)
    {
        dim3 grid(BATCH * HEADS, SEQ_N / 512);
        kv_kernel<<<grid, 256>>>();
    }

    // 4) y = (qf @ kv) / den (fp32)
    {
        dim3 grid(BATCH * HEADS, SEQ_N / 32);
        y_kernel<<<grid, 256>>>();
    }

    // 5) output projection (tf32 tensor cores)
    {
        dim3 grid(CH / 128, M_TOTAL / 128);
        gemm_tf32_kernel<<<grid, 256>>>(y_p, W_out, b_out, (float*)d_out,
                                        M_TOTAL, CH, CH, 0, nullptr);
    }
}